// round 8
// baseline (speedup 1.0000x reference)
#include <cuda_runtime.h>
#include <cuda_fp16.h>
#include <cstdint>

// Problem constants
#define NNODES 50000
#define NEDGES 800000
#define IN_C   256
#define OUT_C  128
#define PAD    96            // max neighbors stored per node (Poisson(16): P(>=96) ~ 1e-40)

// Scratch
__device__ __align__(16) __half g_y[NNODES * OUT_C];   // linear output, fp16 (12.8 MB)
__device__ __align__(16) int g_cnt[NNODES];            // per-node cursor; zero at entry
__device__ __align__(16) int g_pad[NNODES * PAD];      // padded neighbor buckets (19.2 MB)

// ---------------------------------------------------------------------------
// K1: bucket fill — 4 edges per thread, int4 loads, atomic cursor per dst.
// g_cnt is zero on entry (zero-init at load; gather resets it each call).
// ---------------------------------------------------------------------------
__global__ __launch_bounds__(256) void fill_kernel(const int* __restrict__ ei) {
    int t = blockIdx.x * blockDim.x + threadIdx.x;
    int base = t * 4;
    if (base >= NEDGES) return;
    int4 s = *reinterpret_cast<const int4*>(ei + base);
    int4 d = *reinterpret_cast<const int4*>(ei + NEDGES + base);
    int p0 = atomicAdd(&g_cnt[d.x], 1);
    int p1 = atomicAdd(&g_cnt[d.y], 1);
    int p2 = atomicAdd(&g_cnt[d.z], 1);
    int p3 = atomicAdd(&g_cnt[d.w], 1);
    if (p0 < PAD) g_pad[d.x * PAD + p0] = s.x;
    if (p1 < PAD) g_pad[d.y * PAD + p1] = s.y;
    if (p2 < PAD) g_pad[d.z * PAD + p2] = s.z;
    if (p3 < PAD) g_pad[d.w * PAD + p3] = s.w;
}

// ---------------------------------------------------------------------------
// K2: tf32 tensor-core GEMM  y[m,n] = sum_k x[m,k] * W[n,k] + b[n], fp16 out
// ---------------------------------------------------------------------------
#define GBM 128
#define GBK 16
#define SSTRIDE 136

__device__ __forceinline__ uint32_t f32_to_tf32(float f) {
    uint32_t r;
    asm("cvt.rna.tf32.f32 %0, %1;" : "=r"(r) : "f"(f));
    return r;
}

__global__ __launch_bounds__(256) void gemm_tf32_kernel(
    const float* __restrict__ x,
    const float* __restrict__ W,
    const float* __restrict__ b)
{
    __shared__ uint32_t As[GBK * SSTRIDE];
    __shared__ uint32_t Bs[GBK * SSTRIDE];

    const int tid  = threadIdx.x;
    const int lane = tid & 31;
    const int warp = tid >> 5;
    const int wm   = warp >> 1;
    const int wn   = warp & 1;
    const int block_m = blockIdx.x * GBM;
    const int grp = lane >> 2;
    const int qid = lane & 3;

    float acc[2][8][4];
    #pragma unroll
    for (int i = 0; i < 2; i++)
        #pragma unroll
        for (int j = 0; j < 8; j++)
            #pragma unroll
            for (int c = 0; c < 4; c++)
                acc[i][j][c] = 0.f;

    for (int k0 = 0; k0 < IN_C; k0 += GBK) {
        #pragma unroll
        for (int u = 0; u < 2; u++) {
            int idx = tid * 2 + u;
            int row = idx >> 2;
            int kq  = (idx & 3) * 4;

            float4 av = make_float4(0.f, 0.f, 0.f, 0.f);
            int gm = block_m + row;
            if (gm < NNODES)
                av = *reinterpret_cast<const float4*>(x + (size_t)gm * IN_C + k0 + kq);
            As[(kq + 0) * SSTRIDE + row] = f32_to_tf32(av.x);
            As[(kq + 1) * SSTRIDE + row] = f32_to_tf32(av.y);
            As[(kq + 2) * SSTRIDE + row] = f32_to_tf32(av.z);
            As[(kq + 3) * SSTRIDE + row] = f32_to_tf32(av.w);

            float4 bv = *reinterpret_cast<const float4*>(W + (size_t)row * IN_C + k0 + kq);
            Bs[(kq + 0) * SSTRIDE + row] = f32_to_tf32(bv.x);
            Bs[(kq + 1) * SSTRIDE + row] = f32_to_tf32(bv.y);
            Bs[(kq + 2) * SSTRIDE + row] = f32_to_tf32(bv.z);
            Bs[(kq + 3) * SSTRIDE + row] = f32_to_tf32(bv.w);
        }
        __syncthreads();

        #pragma unroll
        for (int s = 0; s < 2; s++) {
            const int kk = s * 8 + qid;

            uint32_t af[2][4];
            #pragma unroll
            for (int i = 0; i < 2; i++) {
                int rm = wm * 32 + i * 16 + grp;
                af[i][0] = As[kk * SSTRIDE + rm];
                af[i][1] = As[kk * SSTRIDE + rm + 8];
                af[i][2] = As[(kk + 4) * SSTRIDE + rm];
                af[i][3] = As[(kk + 4) * SSTRIDE + rm + 8];
            }
            uint32_t bf[8][2];
            #pragma unroll
            for (int j = 0; j < 8; j++) {
                int bn = wn * 64 + j * 8 + grp;
                bf[j][0] = Bs[kk * SSTRIDE + bn];
                bf[j][1] = Bs[(kk + 4) * SSTRIDE + bn];
            }
            #pragma unroll
            for (int i = 0; i < 2; i++)
                #pragma unroll
                for (int j = 0; j < 8; j++) {
                    asm volatile(
                        "mma.sync.aligned.m16n8k8.row.col.f32.tf32.tf32.f32 "
                        "{%0,%1,%2,%3}, {%4,%5,%6,%7}, {%8,%9}, {%0,%1,%2,%3};\n"
                        : "+f"(acc[i][j][0]), "+f"(acc[i][j][1]),
                          "+f"(acc[i][j][2]), "+f"(acc[i][j][3])
                        : "r"(af[i][0]), "r"(af[i][1]), "r"(af[i][2]), "r"(af[i][3]),
                          "r"(bf[j][0]), "r"(bf[j][1]));
                }
        }
        __syncthreads();
    }

    #pragma unroll
    for (int i = 0; i < 2; i++) {
        int r0 = block_m + wm * 32 + i * 16 + grp;
        int r1 = r0 + 8;
        #pragma unroll
        for (int j = 0; j < 8; j++) {
            int col = wn * 64 + j * 8 + qid * 2;
            float b0 = b[col], b1 = b[col + 1];
            if (r0 < NNODES) {
                __half2 h = __floats2half2_rn(acc[i][j][0] + b0, acc[i][j][1] + b1);
                *reinterpret_cast<__half2*>(&g_y[(size_t)r0 * OUT_C + col]) = h;
            }
            if (r1 < NNODES) {
                __half2 h = __floats2half2_rn(acc[i][j][2] + b0, acc[i][j][3] + b1);
                *reinterpret_cast<__half2*>(&g_y[(size_t)r1 * OUT_C + col]) = h;
            }
        }
    }
}

// ---------------------------------------------------------------------------
// K3: gather + mean. 2 nodes per warp; 16 lanes per node; one uint4 (8 halfs)
// per lane. Neighbor ids via int4 loads from the pad row. fp32 accumulation.
// Resets g_cnt[node] = 0 for the next replay.
// ---------------------------------------------------------------------------
__device__ __forceinline__ void acc_row(float* acc, uint4 v) {
    float2 f;
    f = __half22float2(*reinterpret_cast<__half2*>(&v.x)); acc[0] += f.x; acc[1] += f.y;
    f = __half22float2(*reinterpret_cast<__half2*>(&v.y)); acc[2] += f.x; acc[3] += f.y;
    f = __half22float2(*reinterpret_cast<__half2*>(&v.z)); acc[4] += f.x; acc[5] += f.y;
    f = __half22float2(*reinterpret_cast<__half2*>(&v.w)); acc[6] += f.x; acc[7] += f.y;
}

__global__ __launch_bounds__(256) void gather_kernel(float* __restrict__ out) {
    int warp_id = (blockIdx.x * blockDim.x + threadIdx.x) >> 5;
    int lane = threadIdx.x & 31;
    int half_id = lane >> 4;
    int sub = lane & 15;
    int node = warp_id * 2 + half_id;
    if (node >= NNODES) return;

    int cnt = g_cnt[node];
    if (sub == 0) g_cnt[node] = 0;      // restore zero invariant for next call
    int e = min(cnt, PAD);

    float acc[8];
    #pragma unroll
    for (int c = 0; c < 8; c++) acc[c] = 0.f;

    const size_t loff = (size_t)sub * 8;
    const int* prow = &g_pad[node * PAD];

    int i = 0;
    for (; i + 7 < e; i += 8) {
        int4 sa = *reinterpret_cast<const int4*>(prow + i);
        int4 sb = *reinterpret_cast<const int4*>(prow + i + 4);
        uint4 v[8];
        v[0] = *reinterpret_cast<const uint4*>(&g_y[(size_t)sa.x * OUT_C + loff]);
        v[1] = *reinterpret_cast<const uint4*>(&g_y[(size_t)sa.y * OUT_C + loff]);
        v[2] = *reinterpret_cast<const uint4*>(&g_y[(size_t)sa.z * OUT_C + loff]);
        v[3] = *reinterpret_cast<const uint4*>(&g_y[(size_t)sa.w * OUT_C + loff]);
        v[4] = *reinterpret_cast<const uint4*>(&g_y[(size_t)sb.x * OUT_C + loff]);
        v[5] = *reinterpret_cast<const uint4*>(&g_y[(size_t)sb.y * OUT_C + loff]);
        v[6] = *reinterpret_cast<const uint4*>(&g_y[(size_t)sb.z * OUT_C + loff]);
        v[7] = *reinterpret_cast<const uint4*>(&g_y[(size_t)sb.w * OUT_C + loff]);
        #pragma unroll
        for (int q = 0; q < 8; q++) acc_row(acc, v[q]);
    }
    for (; i + 3 < e; i += 4) {
        int4 sa = *reinterpret_cast<const int4*>(prow + i);
        uint4 v[4];
        v[0] = *reinterpret_cast<const uint4*>(&g_y[(size_t)sa.x * OUT_C + loff]);
        v[1] = *reinterpret_cast<const uint4*>(&g_y[(size_t)sa.y * OUT_C + loff]);
        v[2] = *reinterpret_cast<const uint4*>(&g_y[(size_t)sa.z * OUT_C + loff]);
        v[3] = *reinterpret_cast<const uint4*>(&g_y[(size_t)sa.w * OUT_C + loff]);
        #pragma unroll
        for (int q = 0; q < 4; q++) acc_row(acc, v[q]);
    }
    for (; i < e; i++) {
        int s0 = prow[i];
        uint4 v = *reinterpret_cast<const uint4*>(&g_y[(size_t)s0 * OUT_C + loff]);
        acc_row(acc, v);
    }

    float inv = 1.0f / (float)max(cnt, 1);
    float4 o0 = make_float4(acc[0] * inv, acc[1] * inv, acc[2] * inv, acc[3] * inv);
    float4 o1 = make_float4(acc[4] * inv, acc[5] * inv, acc[6] * inv, acc[7] * inv);
    float* op = out + (size_t)node * OUT_C + loff;
    *reinterpret_cast<float4*>(op) = o0;
    *reinterpret_cast<float4*>(op + 4) = o1;
}

// ---------------------------------------------------------------------------
extern "C" void kernel_launch(void* const* d_in, const int* in_sizes, int n_in,
                              void* d_out, int out_size) {
    const float* x  = (const float*)d_in[0];
    const int*   ei = (const int*)d_in[1];
    const float* W  = (const float*)d_in[2];
    const float* b  = (const float*)d_in[3];
    float* out = (float*)d_out;

    static cudaStream_t s_gemm = nullptr;
    static cudaEvent_t ev_fork = nullptr, ev_join = nullptr;
    if (!s_gemm) {
        cudaStreamCreateWithFlags(&s_gemm, cudaStreamNonBlocking);
        cudaEventCreateWithFlags(&ev_fork, cudaEventDisableTiming);
        cudaEventCreateWithFlags(&ev_join, cudaEventDisableTiming);
    }

    int edge_blocks = (NEDGES / 4 + 255) / 256;

    // Fork: GEMM on side stream (independent of bucket fill)
    cudaEventRecord(ev_fork, 0);
    cudaStreamWaitEvent(s_gemm, ev_fork, 0);
    gemm_tf32_kernel<<<(NNODES + GBM - 1) / GBM, 256, 0, s_gemm>>>(x, W, b);
    cudaEventRecord(ev_join, s_gemm);

    // Bucket fill on main stream (g_cnt is zero at entry)
    fill_kernel<<<edge_blocks, 256>>>(ei);

    // Join, then gather + mean
    cudaStreamWaitEvent(0, ev_join, 0);
    gather_kernel<<<(NNODES / 2 * 32 + 255) / 256, 256>>>(out);
}

// round 9
// speedup vs baseline: 1.5226x; 1.5226x over previous
#include <cuda_runtime.h>
#include <cuda_fp16.h>
#include <cstdint>

// Problem constants
#define NNODES 50000
#define NEDGES 800000
#define IN_C   256
#define OUT_C  128
#define NB2    49            // scan blocks: 49 * 1024 = 50176 >= NNODES

// Scratch
__device__ __align__(16) __half g_y[NNODES * OUT_C];  // linear output, fp16
__device__ __align__(16) int g_deg[NNODES];           // zero at entry (consumer-reset)
__device__ __align__(16) int g_off[NNODES + 1];
__device__ __align__(16) int g_cur[NNODES];
__device__ int g_srcs[NEDGES];
// decoupled-lookback scan state; zero at entry (fill resets after scan)
__device__ int g_blk_state[NB2];   // 0=invalid, 1=aggregate ready, 2=prefix ready
__device__ int g_blk_agg[NB2];
__device__ int g_blk_pref[NB2];

// ---------------------------------------------------------------------------
// K1: histogram of dst — 4 edges per thread via int4
// ---------------------------------------------------------------------------
__global__ __launch_bounds__(256) void hist_kernel(const int* __restrict__ ei) {
    int t = blockIdx.x * blockDim.x + threadIdx.x;
    int base = t * 4;
    if (base >= NEDGES) return;
    int4 d = *reinterpret_cast<const int4*>(ei + NEDGES + base);
    atomicAdd(&g_deg[d.x], 1);
    atomicAdd(&g_deg[d.y], 1);
    atomicAdd(&g_deg[d.z], 1);
    atomicAdd(&g_deg[d.w], 1);
}

// ---------------------------------------------------------------------------
// K2: single-pass exclusive scan, warp-parallel decoupled lookback.
// 256 threads x 4 elements = 1024 per block, 49 blocks.
// Also resets g_deg to zero (restores invariant for next call's hist).
// ---------------------------------------------------------------------------
__global__ __launch_bounds__(256) void scan_lookback_kernel() {
    __shared__ int ws[8];
    __shared__ int s_excl;
    const int b = blockIdx.x;
    const int tid = threadIdx.x;
    const int lane = tid & 31, wid = tid >> 5;
    const int i4 = b * 256 + tid;            // int4 index
    const bool inb = (i4 * 4 < NNODES);      // NNODES % 4 == 0

    int4 d = inb ? *reinterpret_cast<const int4*>(&g_deg[i4 * 4])
                 : make_int4(0, 0, 0, 0);
    if (inb)
        *reinterpret_cast<int4*>(&g_deg[i4 * 4]) = make_int4(0, 0, 0, 0);
    int t0 = d.x;
    int t1 = t0 + d.y;
    int t2 = t1 + d.z;
    int t3 = t2 + d.w;                        // thread total

    // block inclusive scan of thread totals
    int incl = t3;
    #pragma unroll
    for (int dd = 1; dd < 32; dd <<= 1) {
        int u = __shfl_up_sync(0xffffffffu, incl, dd);
        if (lane >= dd) incl += u;
    }
    if (lane == 31) ws[wid] = incl;
    __syncthreads();
    if (wid == 0) {
        int s = (lane < 8) ? ws[lane] : 0;
        #pragma unroll
        for (int dd = 1; dd < 8; dd <<= 1) {
            int u = __shfl_up_sync(0xffffffffu, s, dd);
            if (lane >= dd) s += u;
        }
        if (lane < 8) ws[lane] = s;
    }
    __syncthreads();
    int thr_excl = incl - t3 + (wid > 0 ? ws[wid - 1] : 0);
    int total = ws[7];

    // publish aggregate, then warp-parallel lookback (warp 0)
    if (tid == 0) {
        if (b == 0) {
            g_blk_pref[0] = total;
            __threadfence();
            atomicExch(&g_blk_state[0], 2);
        } else {
            g_blk_agg[b] = total;
            __threadfence();
            atomicExch(&g_blk_state[b], 1);
        }
    }
    if (wid == 0) {
        int excl = 0;
        if (b > 0) {
            int hi_end = b;                  // predecessors [0, b)
            while (hi_end > 0) {
                int start = hi_end - 32 > 0 ? hi_end - 32 : 0;
                int idx = start + lane;
                bool valid = (idx < hi_end);
                int st = 2;
                do {
                    if (valid) st = atomicAdd(&g_blk_state[idx], 0);
                } while (__any_sync(0xffffffffu, valid && st == 0));
                int val = 0;
                if (valid)
                    val = (st == 2) ? atomicAdd(&g_blk_pref[idx], 0)
                                    : atomicAdd(&g_blk_agg[idx], 0);
                unsigned m2 = __ballot_sync(0xffffffffu, valid && st == 2);
                int contrib;
                bool done;
                if (m2) {
                    int hi = 31 - __clz(m2);              // rightmost prefix-ready
                    contrib = (valid && lane >= hi) ? val : 0;
                    done = true;
                } else {
                    contrib = valid ? val : 0;
                    done = false;
                }
                #pragma unroll
                for (int dd = 16; dd > 0; dd >>= 1)
                    contrib += __shfl_down_sync(0xffffffffu, contrib, dd);
                excl += __shfl_sync(0xffffffffu, contrib, 0);
                if (done) break;
                hi_end = start;
            }
            if (lane == 0) {
                g_blk_pref[b] = excl + total;
                __threadfence();
                atomicExch(&g_blk_state[b], 2);
            }
        }
        if (lane == 0) s_excl = excl;
    }
    __syncthreads();

    if (inb) {
        int base = s_excl + thr_excl;
        int4 off = make_int4(base, base + t0, base + t1, base + t2);
        *reinterpret_cast<int4*>(&g_off[i4 * 4]) = off;
        *reinterpret_cast<int4*>(&g_cur[i4 * 4]) = off;
    }
    if (b == 0 && tid == 0) g_off[NNODES] = NEDGES;
}

// ---------------------------------------------------------------------------
// K3: bucket fill — 4 edges per thread, int4 loads.
// Also resets the lookback state arrays (after scan has fully completed).
// ---------------------------------------------------------------------------
__global__ __launch_bounds__(256) void fill_kernel(const int* __restrict__ ei) {
    int t = blockIdx.x * blockDim.x + threadIdx.x;
    if (t < NB2) g_blk_state[t] = 0;
    int base = t * 4;
    if (base >= NEDGES) return;
    int4 s = *reinterpret_cast<const int4*>(ei + base);
    int4 d = *reinterpret_cast<const int4*>(ei + NEDGES + base);
    int p0 = atomicAdd(&g_cur[d.x], 1);
    int p1 = atomicAdd(&g_cur[d.y], 1);
    int p2 = atomicAdd(&g_cur[d.z], 1);
    int p3 = atomicAdd(&g_cur[d.w], 1);
    g_srcs[p0] = s.x;
    g_srcs[p1] = s.y;
    g_srcs[p2] = s.z;
    g_srcs[p3] = s.w;
}

// ---------------------------------------------------------------------------
// K4: tf32 tensor-core GEMM, double-buffered smem.
// y[m,n] = sum_k x[m,k] * W[n,k] + b[n], fp16 out.
// BM=128, BN=128, BK=16; 8 warps 4x2; warp tile 32x64 of m16n8k8.
// ---------------------------------------------------------------------------
#define GBM 128
#define GBK 16
#define SSTRIDE 136
#define NTILES (IN_C / GBK)   // 16

__device__ __forceinline__ uint32_t f32_to_tf32(float f) {
    uint32_t r;
    asm("cvt.rna.tf32.f32 %0, %1;" : "=r"(r) : "f"(f));
    return r;
}

__global__ __launch_bounds__(256, 2) void gemm_tf32_kernel(
    const float* __restrict__ x,
    const float* __restrict__ W,
    const float* __restrict__ b)
{
    __shared__ uint32_t As[2][GBK * SSTRIDE];
    __shared__ uint32_t Bs[2][GBK * SSTRIDE];

    const int tid  = threadIdx.x;
    const int lane = tid & 31;
    const int warp = tid >> 5;
    const int wm   = warp >> 1;
    const int wn   = warp & 1;
    const int block_m = blockIdx.x * GBM;
    const int grp = lane >> 2;
    const int qid = lane & 3;

    // load mapping: per u in {0,1}: row 0..127, kq in {0,4,8,12}
    const int idx0 = tid * 2;
    const int row0 = idx0 >> 2;
    const int kq0  = (idx0 & 3) * 4;
    const int row1 = (idx0 + 1) >> 2;
    const int kq1  = ((idx0 + 1) & 3) * 4;
    const int gm0 = block_m + row0;
    const int gm1 = block_m + row1;
    const bool ok0 = (gm0 < NNODES);
    const bool ok1 = (gm1 < NNODES);

    float acc[2][8][4];
    #pragma unroll
    for (int i = 0; i < 2; i++)
        #pragma unroll
        for (int j = 0; j < 8; j++)
            #pragma unroll
            for (int c = 0; c < 4; c++)
                acc[i][j][c] = 0.f;

    float4 pa0, pa1, pb0, pb1;

    // prefetch tile 0
    pa0 = ok0 ? *reinterpret_cast<const float4*>(x + (size_t)gm0 * IN_C + kq0)
              : make_float4(0.f, 0.f, 0.f, 0.f);
    pa1 = ok1 ? *reinterpret_cast<const float4*>(x + (size_t)gm1 * IN_C + kq1)
              : make_float4(0.f, 0.f, 0.f, 0.f);
    pb0 = *reinterpret_cast<const float4*>(W + (size_t)row0 * IN_C + kq0);
    pb1 = *reinterpret_cast<const float4*>(W + (size_t)row1 * IN_C + kq1);

    // store tile 0 into buffer 0
    {
        As[0][(kq0 + 0) * SSTRIDE + row0] = f32_to_tf32(pa0.x);
        As[0][(kq0 + 1) * SSTRIDE + row0] = f32_to_tf32(pa0.y);
        As[0][(kq0 + 2) * SSTRIDE + row0] = f32_to_tf32(pa0.z);
        As[0][(kq0 + 3) * SSTRIDE + row0] = f32_to_tf32(pa0.w);
        As[0][(kq1 + 0) * SSTRIDE + row1] = f32_to_tf32(pa1.x);
        As[0][(kq1 + 1) * SSTRIDE + row1] = f32_to_tf32(pa1.y);
        As[0][(kq1 + 2) * SSTRIDE + row1] = f32_to_tf32(pa1.z);
        As[0][(kq1 + 3) * SSTRIDE + row1] = f32_to_tf32(pa1.w);
        Bs[0][(kq0 + 0) * SSTRIDE + row0] = f32_to_tf32(pb0.x);
        Bs[0][(kq0 + 1) * SSTRIDE + row0] = f32_to_tf32(pb0.y);
        Bs[0][(kq0 + 2) * SSTRIDE + row0] = f32_to_tf32(pb0.z);
        Bs[0][(kq0 + 3) * SSTRIDE + row0] = f32_to_tf32(pb0.w);
        Bs[0][(kq1 + 0) * SSTRIDE + row1] = f32_to_tf32(pb1.x);
        Bs[0][(kq1 + 1) * SSTRIDE + row1] = f32_to_tf32(pb1.y);
        Bs[0][(kq1 + 2) * SSTRIDE + row1] = f32_to_tf32(pb1.z);
        Bs[0][(kq1 + 3) * SSTRIDE + row1] = f32_to_tf32(pb1.w);
    }
    __syncthreads();

    for (int t = 0; t < NTILES; t++) {
        const int cur = t & 1;
        const bool has_next = (t + 1 < NTILES);

        // prefetch next tile (gmem) — overlaps with MMAs below
        if (has_next) {
            int k0 = (t + 1) * GBK;
            pa0 = ok0 ? *reinterpret_cast<const float4*>(x + (size_t)gm0 * IN_C + k0 + kq0)
                      : make_float4(0.f, 0.f, 0.f, 0.f);
            pa1 = ok1 ? *reinterpret_cast<const float4*>(x + (size_t)gm1 * IN_C + k0 + kq1)
                      : make_float4(0.f, 0.f, 0.f, 0.f);
            pb0 = *reinterpret_cast<const float4*>(W + (size_t)row0 * IN_C + k0 + kq0);
            pb1 = *reinterpret_cast<const float4*>(W + (size_t)row1 * IN_C + k0 + kq1);
        }

        // compute on current buffer
        #pragma unroll
        for (int s = 0; s < 2; s++) {
            const int kk = s * 8 + qid;

            uint32_t af[2][4];
            #pragma unroll
            for (int i = 0; i < 2; i++) {
                int rm = wm * 32 + i * 16 + grp;
                af[i][0] = As[cur][kk * SSTRIDE + rm];
                af[i][1] = As[cur][kk * SSTRIDE + rm + 8];
                af[i][2] = As[cur][(kk + 4) * SSTRIDE + rm];
                af[i][3] = As[cur][(kk + 4) * SSTRIDE + rm + 8];
            }
            uint32_t bf[8][2];
            #pragma unroll
            for (int j = 0; j < 8; j++) {
                int bn = wn * 64 + j * 8 + grp;
                bf[j][0] = Bs[cur][kk * SSTRIDE + bn];
                bf[j][1] = Bs[cur][(kk + 4) * SSTRIDE + bn];
            }
            #pragma unroll
            for (int i = 0; i < 2; i++)
                #pragma unroll
                for (int j = 0; j < 8; j++) {
                    asm volatile(
                        "mma.sync.aligned.m16n8k8.row.col.f32.tf32.tf32.f32 "
                        "{%0,%1,%2,%3}, {%4,%5,%6,%7}, {%8,%9}, {%0,%1,%2,%3};\n"
                        : "+f"(acc[i][j][0]), "+f"(acc[i][j][1]),
                          "+f"(acc[i][j][2]), "+f"(acc[i][j][3])
                        : "r"(af[i][0]), "r"(af[i][1]), "r"(af[i][2]), "r"(af[i][3]),
                          "r"(bf[j][0]), "r"(bf[j][1]));
                }
        }

        // store prefetched tile into the other buffer
        if (has_next) {
            const int nxt = cur ^ 1;
            As[nxt][(kq0 + 0) * SSTRIDE + row0] = f32_to_tf32(pa0.x);
            As[nxt][(kq0 + 1) * SSTRIDE + row0] = f32_to_tf32(pa0.y);
            As[nxt][(kq0 + 2) * SSTRIDE + row0] = f32_to_tf32(pa0.z);
            As[nxt][(kq0 + 3) * SSTRIDE + row0] = f32_to_tf32(pa0.w);
            As[nxt][(kq1 + 0) * SSTRIDE + row1] = f32_to_tf32(pa1.x);
            As[nxt][(kq1 + 1) * SSTRIDE + row1] = f32_to_tf32(pa1.y);
            As[nxt][(kq1 + 2) * SSTRIDE + row1] = f32_to_tf32(pa1.z);
            As[nxt][(kq1 + 3) * SSTRIDE + row1] = f32_to_tf32(pa1.w);
            Bs[nxt][(kq0 + 0) * SSTRIDE + row0] = f32_to_tf32(pb0.x);
            Bs[nxt][(kq0 + 1) * SSTRIDE + row0] = f32_to_tf32(pb0.y);
            Bs[nxt][(kq0 + 2) * SSTRIDE + row0] = f32_to_tf32(pb0.z);
            Bs[nxt][(kq0 + 3) * SSTRIDE + row0] = f32_to_tf32(pb0.w);
            Bs[nxt][(kq1 + 0) * SSTRIDE + row1] = f32_to_tf32(pb1.x);
            Bs[nxt][(kq1 + 1) * SSTRIDE + row1] = f32_to_tf32(pb1.y);
            Bs[nxt][(kq1 + 2) * SSTRIDE + row1] = f32_to_tf32(pb1.z);
            Bs[nxt][(kq1 + 3) * SSTRIDE + row1] = f32_to_tf32(pb1.w);
            __syncthreads();
        }
    }

    // Epilogue: bias + fp16 store
    #pragma unroll
    for (int i = 0; i < 2; i++) {
        int r0 = block_m + wm * 32 + i * 16 + grp;
        int r1 = r0 + 8;
        #pragma unroll
        for (int j = 0; j < 8; j++) {
            int col = wn * 64 + j * 8 + qid * 2;
            float b0 = b[col], b1 = b[col + 1];
            if (r0 < NNODES) {
                __half2 h = __floats2half2_rn(acc[i][j][0] + b0, acc[i][j][1] + b1);
                *reinterpret_cast<__half2*>(&g_y[(size_t)r0 * OUT_C + col]) = h;
            }
            if (r1 < NNODES) {
                __half2 h = __floats2half2_rn(acc[i][j][2] + b0, acc[i][j][3] + b1);
                *reinterpret_cast<__half2*>(&g_y[(size_t)r1 * OUT_C + col]) = h;
            }
        }
    }
}

// ---------------------------------------------------------------------------
// K5: gather + mean. 2 nodes per warp; 16 lanes per node; one uint4 (8 halfs)
// per lane. fp32 accumulation, unrolled x8 for MLP.
// ---------------------------------------------------------------------------
__device__ __forceinline__ void acc_row(float* acc, uint4 v) {
    float2 f;
    f = __half22float2(*reinterpret_cast<__half2*>(&v.x)); acc[0] += f.x; acc[1] += f.y;
    f = __half22float2(*reinterpret_cast<__half2*>(&v.y)); acc[2] += f.x; acc[3] += f.y;
    f = __half22float2(*reinterpret_cast<__half2*>(&v.z)); acc[4] += f.x; acc[5] += f.y;
    f = __half22float2(*reinterpret_cast<__half2*>(&v.w)); acc[6] += f.x; acc[7] += f.y;
}

__global__ __launch_bounds__(256) void gather_kernel(float* __restrict__ out) {
    int warp_id = (blockIdx.x * blockDim.x + threadIdx.x) >> 5;
    int lane = threadIdx.x & 31;
    int half_id = lane >> 4;
    int sub = lane & 15;
    int node = warp_id * 2 + half_id;
    if (node >= NNODES) return;

    int s = g_off[node];
    int e = g_off[node + 1];

    float acc[8];
    #pragma unroll
    for (int c = 0; c < 8; c++) acc[c] = 0.f;

    const size_t loff = (size_t)sub * 8;

    int i = s;
    for (; i + 7 < e; i += 8) {
        int sn[8];
        #pragma unroll
        for (int q = 0; q < 8; q++) sn[q] = __ldg(&g_srcs[i + q]);
        uint4 v[8];
        #pragma unroll
        for (int q = 0; q < 8; q++)
            v[q] = *reinterpret_cast<const uint4*>(&g_y[(size_t)sn[q] * OUT_C + loff]);
        #pragma unroll
        for (int q = 0; q < 8; q++) acc_row(acc, v[q]);
    }
    for (; i + 3 < e; i += 4) {
        int sn[4];
        #pragma unroll
        for (int q = 0; q < 4; q++) sn[q] = __ldg(&g_srcs[i + q]);
        uint4 v[4];
        #pragma unroll
        for (int q = 0; q < 4; q++)
            v[q] = *reinterpret_cast<const uint4*>(&g_y[(size_t)sn[q] * OUT_C + loff]);
        #pragma unroll
        for (int q = 0; q < 4; q++) acc_row(acc, v[q]);
    }
    for (; i < e; i++) {
        int s0 = __ldg(&g_srcs[i]);
        uint4 v = *reinterpret_cast<const uint4*>(&g_y[(size_t)s0 * OUT_C + loff]);
        acc_row(acc, v);
    }

    float inv = 1.0f / (float)max(e - s, 1);
    float4 o0 = make_float4(acc[0] * inv, acc[1] * inv, acc[2] * inv, acc[3] * inv);
    float4 o1 = make_float4(acc[4] * inv, acc[5] * inv, acc[6] * inv, acc[7] * inv);
    float* op = out + (size_t)node * OUT_C + loff;
    *reinterpret_cast<float4*>(op) = o0;
    *reinterpret_cast<float4*>(op + 4) = o1;
}

// ---------------------------------------------------------------------------
extern "C" void kernel_launch(void* const* d_in, const int* in_sizes, int n_in,
                              void* d_out, int out_size) {
    const float* x  = (const float*)d_in[0];
    const int*   ei = (const int*)d_in[1];
    const float* W  = (const float*)d_in[2];
    const float* b  = (const float*)d_in[3];
    float* out = (float*)d_out;

    static cudaStream_t s_gemm = nullptr;
    static cudaEvent_t ev_fork = nullptr, ev_join = nullptr;
    if (!s_gemm) {
        cudaStreamCreateWithFlags(&s_gemm, cudaStreamNonBlocking);
        cudaEventCreateWithFlags(&ev_fork, cudaEventDisableTiming);
        cudaEventCreateWithFlags(&ev_join, cudaEventDisableTiming);
    }

    int edge_blocks = (NEDGES / 4 + 255) / 256;

    // Fork: GEMM on side stream (independent of CSR build)
    cudaEventRecord(ev_fork, 0);
    cudaStreamWaitEvent(s_gemm, ev_fork, 0);
    gemm_tf32_kernel<<<(NNODES + GBM - 1) / GBM, 256, 0, s_gemm>>>(x, W, b);
    cudaEventRecord(ev_join, s_gemm);

    // CSR build on main stream (g_deg, g_blk_state are zero at entry)
    hist_kernel<<<edge_blocks, 256>>>(ei);
    scan_lookback_kernel<<<NB2, 256>>>();
    fill_kernel<<<edge_blocks, 256>>>(ei);

    // Join, then gather + mean
    cudaStreamWaitEvent(0, ev_join, 0);
    gather_kernel<<<(NNODES / 2 * 32 + 255) / 256, 256>>>(out);
}

// round 10
// speedup vs baseline: 1.5447x; 1.0145x over previous
#include <cuda_runtime.h>
#include <cuda_fp16.h>
#include <cstdint>

// Problem constants
#define NNODES 50000
#define NEDGES 800000
#define IN_C   256
#define OUT_C  128
#define NB3    25            // scan blocks: 25 * 2048 = 51200 >= NNODES

// Scratch
__device__ __align__(16) __half g_y[NNODES * OUT_C];  // linear output, fp16
__device__ __align__(16) int g_deg[NNODES];           // zero at entry (consumer-reset)
__device__ __align__(16) int g_off[NNODES + 1];
__device__ __align__(16) int g_cur[NNODES];
__device__ int g_srcs[NEDGES];
// decoupled-lookback scan state; zero at entry (fill resets after scan)
__device__ int g_blk_state[NB3];   // 0=invalid, 1=aggregate ready, 2=prefix ready
__device__ int g_blk_agg[NB3];
__device__ int g_blk_pref[NB3];

// ---------------------------------------------------------------------------
// K1: histogram of dst — 8 edges per thread via 2x int4
// ---------------------------------------------------------------------------
__global__ __launch_bounds__(256) void hist_kernel(const int* __restrict__ ei) {
    int t = blockIdx.x * blockDim.x + threadIdx.x;
    int base = t * 8;
    if (base >= NEDGES) return;
    int4 d0 = *reinterpret_cast<const int4*>(ei + NEDGES + base);
    int4 d1 = *reinterpret_cast<const int4*>(ei + NEDGES + base + 4);
    atomicAdd(&g_deg[d0.x], 1);
    atomicAdd(&g_deg[d0.y], 1);
    atomicAdd(&g_deg[d0.z], 1);
    atomicAdd(&g_deg[d0.w], 1);
    atomicAdd(&g_deg[d1.x], 1);
    atomicAdd(&g_deg[d1.y], 1);
    atomicAdd(&g_deg[d1.z], 1);
    atomicAdd(&g_deg[d1.w], 1);
}

// ---------------------------------------------------------------------------
// K2: single-pass exclusive scan, warp-parallel decoupled lookback.
// 256 threads x 8 elements = 2048 per block, 25 blocks.
// Also resets g_deg to zero (restores invariant for next call's hist).
// ---------------------------------------------------------------------------
__global__ __launch_bounds__(256) void scan_lookback_kernel() {
    __shared__ int ws[8];
    __shared__ int s_excl;
    const int b = blockIdx.x;
    const int tid = threadIdx.x;
    const int lane = tid & 31, wid = tid >> 5;
    const int e0 = (b * 256 + tid) * 8;      // element base (8 per thread)
    const bool inb0 = (e0 < NNODES);         // NNODES % 8 == 0
    // Note: NNODES = 50000; 50000/8 = 6250 exactly, so either all 8 in-bounds
    // or all out (e0 multiple of 8; 50000 % 8 == 0).

    int4 da = inb0 ? *reinterpret_cast<const int4*>(&g_deg[e0])
                   : make_int4(0, 0, 0, 0);
    int4 db = inb0 ? *reinterpret_cast<const int4*>(&g_deg[e0 + 4])
                   : make_int4(0, 0, 0, 0);
    if (inb0) {
        *reinterpret_cast<int4*>(&g_deg[e0]) = make_int4(0, 0, 0, 0);
        *reinterpret_cast<int4*>(&g_deg[e0 + 4]) = make_int4(0, 0, 0, 0);
    }
    int p0 = da.x;
    int p1 = p0 + da.y;
    int p2 = p1 + da.z;
    int p3 = p2 + da.w;
    int p4 = p3 + db.x;
    int p5 = p4 + db.y;
    int p6 = p5 + db.z;
    int p7 = p6 + db.w;                      // thread total

    // block inclusive scan of thread totals
    int incl = p7;
    #pragma unroll
    for (int dd = 1; dd < 32; dd <<= 1) {
        int u = __shfl_up_sync(0xffffffffu, incl, dd);
        if (lane >= dd) incl += u;
    }
    if (lane == 31) ws[wid] = incl;
    __syncthreads();
    if (wid == 0) {
        int s = (lane < 8) ? ws[lane] : 0;
        #pragma unroll
        for (int dd = 1; dd < 8; dd <<= 1) {
            int u = __shfl_up_sync(0xffffffffu, s, dd);
            if (lane >= dd) s += u;
        }
        if (lane < 8) ws[lane] = s;
    }
    __syncthreads();
    int thr_excl = incl - p7 + (wid > 0 ? ws[wid - 1] : 0);
    int total = ws[7];

    // publish aggregate, then warp-parallel lookback (warp 0)
    if (tid == 0) {
        if (b == 0) {
            g_blk_pref[0] = total;
            __threadfence();
            atomicExch(&g_blk_state[0], 2);
        } else {
            g_blk_agg[b] = total;
            __threadfence();
            atomicExch(&g_blk_state[b], 1);
        }
    }
    if (wid == 0) {
        int excl = 0;
        if (b > 0) {
            int hi_end = b;                  // predecessors [0, b), <= 24
            while (hi_end > 0) {
                int start = hi_end - 32 > 0 ? hi_end - 32 : 0;
                int idx = start + lane;
                bool valid = (idx < hi_end);
                int st = 2;
                do {
                    if (valid) st = atomicAdd(&g_blk_state[idx], 0);
                } while (__any_sync(0xffffffffu, valid && st == 0));
                int val = 0;
                if (valid)
                    val = (st == 2) ? atomicAdd(&g_blk_pref[idx], 0)
                                    : atomicAdd(&g_blk_agg[idx], 0);
                unsigned m2 = __ballot_sync(0xffffffffu, valid && st == 2);
                int contrib;
                bool done;
                if (m2) {
                    int hi = 31 - __clz(m2);              // rightmost prefix-ready
                    contrib = (valid && lane >= hi) ? val : 0;
                    done = true;
                } else {
                    contrib = valid ? val : 0;
                    done = false;
                }
                #pragma unroll
                for (int dd = 16; dd > 0; dd >>= 1)
                    contrib += __shfl_down_sync(0xffffffffu, contrib, dd);
                excl += __shfl_sync(0xffffffffu, contrib, 0);
                if (done) break;
                hi_end = start;
            }
            if (lane == 0) {
                g_blk_pref[b] = excl + total;
                __threadfence();
                atomicExch(&g_blk_state[b], 2);
            }
        }
        if (lane == 0) s_excl = excl;
    }
    __syncthreads();

    if (inb0) {
        int base = s_excl + thr_excl;
        int4 oa = make_int4(base, base + p0, base + p1, base + p2);
        int4 ob = make_int4(base + p3, base + p4, base + p5, base + p6);
        *reinterpret_cast<int4*>(&g_off[e0]) = oa;
        *reinterpret_cast<int4*>(&g_off[e0 + 4]) = ob;
        *reinterpret_cast<int4*>(&g_cur[e0]) = oa;
        *reinterpret_cast<int4*>(&g_cur[e0 + 4]) = ob;
    }
    if (b == 0 && tid == 0) g_off[NNODES] = NEDGES;
}

// ---------------------------------------------------------------------------
// K3: bucket fill — 8 edges per thread, 2x int4 loads.
// Also resets the lookback state arrays (after scan has fully completed).
// ---------------------------------------------------------------------------
__global__ __launch_bounds__(256) void fill_kernel(const int* __restrict__ ei) {
    int t = blockIdx.x * blockDim.x + threadIdx.x;
    if (t < NB3) g_blk_state[t] = 0;
    int base = t * 8;
    if (base >= NEDGES) return;
    int4 s0 = *reinterpret_cast<const int4*>(ei + base);
    int4 s1 = *reinterpret_cast<const int4*>(ei + base + 4);
    int4 d0 = *reinterpret_cast<const int4*>(ei + NEDGES + base);
    int4 d1 = *reinterpret_cast<const int4*>(ei + NEDGES + base + 4);
    int q0 = atomicAdd(&g_cur[d0.x], 1);
    int q1 = atomicAdd(&g_cur[d0.y], 1);
    int q2 = atomicAdd(&g_cur[d0.z], 1);
    int q3 = atomicAdd(&g_cur[d0.w], 1);
    int q4 = atomicAdd(&g_cur[d1.x], 1);
    int q5 = atomicAdd(&g_cur[d1.y], 1);
    int q6 = atomicAdd(&g_cur[d1.z], 1);
    int q7 = atomicAdd(&g_cur[d1.w], 1);
    g_srcs[q0] = s0.x;
    g_srcs[q1] = s0.y;
    g_srcs[q2] = s0.z;
    g_srcs[q3] = s0.w;
    g_srcs[q4] = s1.x;
    g_srcs[q5] = s1.y;
    g_srcs[q6] = s1.z;
    g_srcs[q7] = s1.w;
}

// ---------------------------------------------------------------------------
// K4: tf32 tensor-core GEMM, double-buffered smem.
// y[m,n] = sum_k x[m,k] * W[n,k] + b[n], fp16 out.
// ---------------------------------------------------------------------------
#define GBM 128
#define GBK 16
#define SSTRIDE 136
#define NTILES (IN_C / GBK)   // 16

__device__ __forceinline__ uint32_t f32_to_tf32(float f) {
    uint32_t r;
    asm("cvt.rna.tf32.f32 %0, %1;" : "=r"(r) : "f"(f));
    return r;
}

__global__ __launch_bounds__(256, 2) void gemm_tf32_kernel(
    const float* __restrict__ x,
    const float* __restrict__ W,
    const float* __restrict__ b)
{
    __shared__ uint32_t As[2][GBK * SSTRIDE];
    __shared__ uint32_t Bs[2][GBK * SSTRIDE];

    const int tid  = threadIdx.x;
    const int lane = tid & 31;
    const int warp = tid >> 5;
    const int wm   = warp >> 1;
    const int wn   = warp & 1;
    const int block_m = blockIdx.x * GBM;
    const int grp = lane >> 2;
    const int qid = lane & 3;

    const int idx0 = tid * 2;
    const int row0 = idx0 >> 2;
    const int kq0  = (idx0 & 3) * 4;
    const int row1 = (idx0 + 1) >> 2;
    const int kq1  = ((idx0 + 1) & 3) * 4;
    const int gm0 = block_m + row0;
    const int gm1 = block_m + row1;
    const bool ok0 = (gm0 < NNODES);
    const bool ok1 = (gm1 < NNODES);

    float acc[2][8][4];
    #pragma unroll
    for (int i = 0; i < 2; i++)
        #pragma unroll
        for (int j = 0; j < 8; j++)
            #pragma unroll
            for (int c = 0; c < 4; c++)
                acc[i][j][c] = 0.f;

    float4 pa0, pa1, pb0, pb1;

    pa0 = ok0 ? *reinterpret_cast<const float4*>(x + (size_t)gm0 * IN_C + kq0)
              : make_float4(0.f, 0.f, 0.f, 0.f);
    pa1 = ok1 ? *reinterpret_cast<const float4*>(x + (size_t)gm1 * IN_C + kq1)
              : make_float4(0.f, 0.f, 0.f, 0.f);
    pb0 = *reinterpret_cast<const float4*>(W + (size_t)row0 * IN_C + kq0);
    pb1 = *reinterpret_cast<const float4*>(W + (size_t)row1 * IN_C + kq1);

    {
        As[0][(kq0 + 0) * SSTRIDE + row0] = f32_to_tf32(pa0.x);
        As[0][(kq0 + 1) * SSTRIDE + row0] = f32_to_tf32(pa0.y);
        As[0][(kq0 + 2) * SSTRIDE + row0] = f32_to_tf32(pa0.z);
        As[0][(kq0 + 3) * SSTRIDE + row0] = f32_to_tf32(pa0.w);
        As[0][(kq1 + 0) * SSTRIDE + row1] = f32_to_tf32(pa1.x);
        As[0][(kq1 + 1) * SSTRIDE + row1] = f32_to_tf32(pa1.y);
        As[0][(kq1 + 2) * SSTRIDE + row1] = f32_to_tf32(pa1.z);
        As[0][(kq1 + 3) * SSTRIDE + row1] = f32_to_tf32(pa1.w);
        Bs[0][(kq0 + 0) * SSTRIDE + row0] = f32_to_tf32(pb0.x);
        Bs[0][(kq0 + 1) * SSTRIDE + row0] = f32_to_tf32(pb0.y);
        Bs[0][(kq0 + 2) * SSTRIDE + row0] = f32_to_tf32(pb0.z);
        Bs[0][(kq0 + 3) * SSTRIDE + row0] = f32_to_tf32(pb0.w);
        Bs[0][(kq1 + 0) * SSTRIDE + row1] = f32_to_tf32(pb1.x);
        Bs[0][(kq1 + 1) * SSTRIDE + row1] = f32_to_tf32(pb1.y);
        Bs[0][(kq1 + 2) * SSTRIDE + row1] = f32_to_tf32(pb1.z);
        Bs[0][(kq1 + 3) * SSTRIDE + row1] = f32_to_tf32(pb1.w);
    }
    __syncthreads();

    for (int t = 0; t < NTILES; t++) {
        const int cur = t & 1;
        const bool has_next = (t + 1 < NTILES);

        if (has_next) {
            int k0 = (t + 1) * GBK;
            pa0 = ok0 ? *reinterpret_cast<const float4*>(x + (size_t)gm0 * IN_C + k0 + kq0)
                      : make_float4(0.f, 0.f, 0.f, 0.f);
            pa1 = ok1 ? *reinterpret_cast<const float4*>(x + (size_t)gm1 * IN_C + k0 + kq1)
                      : make_float4(0.f, 0.f, 0.f, 0.f);
            pb0 = *reinterpret_cast<const float4*>(W + (size_t)row0 * IN_C + k0 + kq0);
            pb1 = *reinterpret_cast<const float4*>(W + (size_t)row1 * IN_C + k0 + kq1);
        }

        #pragma unroll
        for (int s = 0; s < 2; s++) {
            const int kk = s * 8 + qid;

            uint32_t af[2][4];
            #pragma unroll
            for (int i = 0; i < 2; i++) {
                int rm = wm * 32 + i * 16 + grp;
                af[i][0] = As[cur][kk * SSTRIDE + rm];
                af[i][1] = As[cur][kk * SSTRIDE + rm + 8];
                af[i][2] = As[cur][(kk + 4) * SSTRIDE + rm];
                af[i][3] = As[cur][(kk + 4) * SSTRIDE + rm + 8];
            }
            uint32_t bf[8][2];
            #pragma unroll
            for (int j = 0; j < 8; j++) {
                int bn = wn * 64 + j * 8 + grp;
                bf[j][0] = Bs[cur][kk * SSTRIDE + bn];
                bf[j][1] = Bs[cur][(kk + 4) * SSTRIDE + bn];
            }
            #pragma unroll
            for (int i = 0; i < 2; i++)
                #pragma unroll
                for (int j = 0; j < 8; j++) {
                    asm volatile(
                        "mma.sync.aligned.m16n8k8.row.col.f32.tf32.tf32.f32 "
                        "{%0,%1,%2,%3}, {%4,%5,%6,%7}, {%8,%9}, {%0,%1,%2,%3};\n"
                        : "+f"(acc[i][j][0]), "+f"(acc[i][j][1]),
                          "+f"(acc[i][j][2]), "+f"(acc[i][j][3])
                        : "r"(af[i][0]), "r"(af[i][1]), "r"(af[i][2]), "r"(af[i][3]),
                          "r"(bf[j][0]), "r"(bf[j][1]));
                }
        }

        if (has_next) {
            const int nxt = cur ^ 1;
            As[nxt][(kq0 + 0) * SSTRIDE + row0] = f32_to_tf32(pa0.x);
            As[nxt][(kq0 + 1) * SSTRIDE + row0] = f32_to_tf32(pa0.y);
            As[nxt][(kq0 + 2) * SSTRIDE + row0] = f32_to_tf32(pa0.z);
            As[nxt][(kq0 + 3) * SSTRIDE + row0] = f32_to_tf32(pa0.w);
            As[nxt][(kq1 + 0) * SSTRIDE + row1] = f32_to_tf32(pa1.x);
            As[nxt][(kq1 + 1) * SSTRIDE + row1] = f32_to_tf32(pa1.y);
            As[nxt][(kq1 + 2) * SSTRIDE + row1] = f32_to_tf32(pa1.z);
            As[nxt][(kq1 + 3) * SSTRIDE + row1] = f32_to_tf32(pa1.w);
            Bs[nxt][(kq0 + 0) * SSTRIDE + row0] = f32_to_tf32(pb0.x);
            Bs[nxt][(kq0 + 1) * SSTRIDE + row0] = f32_to_tf32(pb0.y);
            Bs[nxt][(kq0 + 2) * SSTRIDE + row0] = f32_to_tf32(pb0.z);
            Bs[nxt][(kq0 + 3) * SSTRIDE + row0] = f32_to_tf32(pb0.w);
            Bs[nxt][(kq1 + 0) * SSTRIDE + row1] = f32_to_tf32(pb1.x);
            Bs[nxt][(kq1 + 1) * SSTRIDE + row1] = f32_to_tf32(pb1.y);
            Bs[nxt][(kq1 + 2) * SSTRIDE + row1] = f32_to_tf32(pb1.z);
            Bs[nxt][(kq1 + 3) * SSTRIDE + row1] = f32_to_tf32(pb1.w);
            __syncthreads();
        }
    }

    #pragma unroll
    for (int i = 0; i < 2; i++) {
        int r0 = block_m + wm * 32 + i * 16 + grp;
        int r1 = r0 + 8;
        #pragma unroll
        for (int j = 0; j < 8; j++) {
            int col = wn * 64 + j * 8 + qid * 2;
            float b0 = b[col], b1 = b[col + 1];
            if (r0 < NNODES) {
                __half2 h = __floats2half2_rn(acc[i][j][0] + b0, acc[i][j][1] + b1);
                *reinterpret_cast<__half2*>(&g_y[(size_t)r0 * OUT_C + col]) = h;
            }
            if (r1 < NNODES) {
                __half2 h = __floats2half2_rn(acc[i][j][2] + b0, acc[i][j][3] + b1);
                *reinterpret_cast<__half2*>(&g_y[(size_t)r1 * OUT_C + col]) = h;
            }
        }
    }
}

// ---------------------------------------------------------------------------
// K5: gather + mean. 2 nodes per warp; 16 lanes per node; one uint4 (8 halfs)
// per lane. fp32 accumulation; software-pipelined 8-deep.
// ---------------------------------------------------------------------------
__device__ __forceinline__ void acc_row(float* acc, uint4 v) {
    float2 f;
    f = __half22float2(*reinterpret_cast<__half2*>(&v.x)); acc[0] += f.x; acc[1] += f.y;
    f = __half22float2(*reinterpret_cast<__half2*>(&v.y)); acc[2] += f.x; acc[3] += f.y;
    f = __half22float2(*reinterpret_cast<__half2*>(&v.z)); acc[4] += f.x; acc[5] += f.y;
    f = __half22float2(*reinterpret_cast<__half2*>(&v.w)); acc[6] += f.x; acc[7] += f.y;
}

__global__ __launch_bounds__(256) void gather_kernel(float* __restrict__ out) {
    int warp_id = (blockIdx.x * blockDim.x + threadIdx.x) >> 5;
    int lane = threadIdx.x & 31;
    int half_id = lane >> 4;
    int sub = lane & 15;
    int node = warp_id * 2 + half_id;
    if (node >= NNODES) return;

    int s = g_off[node];
    int e = g_off[node + 1];

    float acc[8];
    #pragma unroll
    for (int c = 0; c < 8; c++) acc[c] = 0.f;

    const size_t loff = (size_t)sub * 8;

    int i = s;
    for (; i + 7 < e; i += 8) {
        int sn[8];
        #pragma unroll
        for (int q = 0; q < 8; q++) sn[q] = __ldg(&g_srcs[i + q]);
        uint4 v[8];
        #pragma unroll
        for (int q = 0; q < 8; q++)
            v[q] = *reinterpret_cast<const uint4*>(&g_y[(size_t)sn[q] * OUT_C + loff]);
        #pragma unroll
        for (int q = 0; q < 8; q++) acc_row(acc, v[q]);
    }
    for (; i + 3 < e; i += 4) {
        int sn[4];
        #pragma unroll
        for (int q = 0; q < 4; q++) sn[q] = __ldg(&g_srcs[i + q]);
        uint4 v[4];
        #pragma unroll
        for (int q = 0; q < 4; q++)
            v[q] = *reinterpret_cast<const uint4*>(&g_y[(size_t)sn[q] * OUT_C + loff]);
        #pragma unroll
        for (int q = 0; q < 4; q++) acc_row(acc, v[q]);
    }
    for (; i < e; i++) {
        int s0 = __ldg(&g_srcs[i]);
        uint4 v = *reinterpret_cast<const uint4*>(&g_y[(size_t)s0 * OUT_C + loff]);
        acc_row(acc, v);
    }

    float inv = 1.0f / (float)max(e - s, 1);
    float4 o0 = make_float4(acc[0] * inv, acc[1] * inv, acc[2] * inv, acc[3] * inv);
    float4 o1 = make_float4(acc[4] * inv, acc[5] * inv, acc[6] * inv, acc[7] * inv);
    float* op = out + (size_t)node * OUT_C + loff;
    *reinterpret_cast<float4*>(op) = o0;
    *reinterpret_cast<float4*>(op + 4) = o1;
}

// ---------------------------------------------------------------------------
extern "C" void kernel_launch(void* const* d_in, const int* in_sizes, int n_in,
                              void* d_out, int out_size) {
    const float* x  = (const float*)d_in[0];
    const int*   ei = (const int*)d_in[1];
    const float* W  = (const float*)d_in[2];
    const float* b  = (const float*)d_in[3];
    float* out = (float*)d_out;

    static cudaStream_t s_gemm = nullptr;
    static cudaEvent_t ev_fork = nullptr, ev_join = nullptr;
    if (!s_gemm) {
        cudaStreamCreateWithFlags(&s_gemm, cudaStreamNonBlocking);
        cudaEventCreateWithFlags(&ev_fork, cudaEventDisableTiming);
        cudaEventCreateWithFlags(&ev_join, cudaEventDisableTiming);
    }

    int edge_blocks8 = (NEDGES / 8 + 255) / 256;   // 8 edges per thread

    // Fork: GEMM on side stream (independent of CSR build)
    cudaEventRecord(ev_fork, 0);
    cudaStreamWaitEvent(s_gemm, ev_fork, 0);
    gemm_tf32_kernel<<<(NNODES + GBM - 1) / GBM, 256, 0, s_gemm>>>(x, W, b);
    cudaEventRecord(ev_join, s_gemm);

    // CSR build on main stream (g_deg, g_blk_state are zero at entry)
    hist_kernel<<<edge_blocks8, 256>>>(ei);
    scan_lookback_kernel<<<NB3, 256>>>();
    fill_kernel<<<edge_blocks8, 256>>>(ei);

    // Join, then gather + mean
    cudaStreamWaitEvent(0, ev_join, 0);
    gather_kernel<<<(NNODES / 2 * 32 + 255) / 256, 256>>>(out);
}

// round 11
// speedup vs baseline: 1.5720x; 1.0176x over previous
#include <cuda_runtime.h>
#include <cuda_fp16.h>
#include <cstdint>

// Problem constants
#define NNODES 50000
#define NEDGES 800000
#define IN_C   256
#define OUT_C  128
#define NB3    25            // scan blocks: 25 * 2048 = 51200 >= NNODES

// Scratch
__device__ __align__(16) __half g_y[NNODES * OUT_C];  // linear output, fp16
__device__ __align__(16) int g_deg[NNODES];           // zero at entry (consumer-reset)
__device__ __align__(16) int g_off[NNODES + 1];
__device__ __align__(16) int g_rank[NEDGES];          // rank of edge within dst bucket
__device__ int g_srcs[NEDGES];
// decoupled-lookback scan state; zero at entry (fill resets after scan)
__device__ int g_blk_state[NB3];   // 0=invalid, 1=aggregate ready, 2=prefix ready
__device__ int g_blk_agg[NB3];
__device__ int g_blk_pref[NB3];

// ---------------------------------------------------------------------------
// K1: rank kernel — THE single atomic pass. r = old count of dst; also the
// histogram. 4 edges per thread via int4; ranks stored coalesced.
// ---------------------------------------------------------------------------
__global__ __launch_bounds__(256) void rank_kernel(const int* __restrict__ ei) {
    int t = blockIdx.x * blockDim.x + threadIdx.x;
    int base = t * 4;
    if (base >= NEDGES) return;
    int4 d = *reinterpret_cast<const int4*>(ei + NEDGES + base);
    int4 r;
    r.x = atomicAdd(&g_deg[d.x], 1);
    r.y = atomicAdd(&g_deg[d.y], 1);
    r.z = atomicAdd(&g_deg[d.z], 1);
    r.w = atomicAdd(&g_deg[d.w], 1);
    *reinterpret_cast<int4*>(&g_rank[base]) = r;
}

// ---------------------------------------------------------------------------
// K2: single-pass exclusive scan, warp-parallel decoupled lookback.
// 256 threads x 8 elements = 2048 per block, 25 blocks.
// Also resets g_deg to zero (restores invariant for next call's rank pass).
// ---------------------------------------------------------------------------
__global__ __launch_bounds__(256) void scan_lookback_kernel() {
    __shared__ int ws[8];
    __shared__ int s_excl;
    const int b = blockIdx.x;
    const int tid = threadIdx.x;
    const int lane = tid & 31, wid = tid >> 5;
    const int e0 = (b * 256 + tid) * 8;      // element base (8 per thread)
    const bool inb0 = (e0 < NNODES);         // NNODES % 8 == 0

    int4 da = inb0 ? *reinterpret_cast<const int4*>(&g_deg[e0])
                   : make_int4(0, 0, 0, 0);
    int4 db = inb0 ? *reinterpret_cast<const int4*>(&g_deg[e0 + 4])
                   : make_int4(0, 0, 0, 0);
    if (inb0) {
        *reinterpret_cast<int4*>(&g_deg[e0]) = make_int4(0, 0, 0, 0);
        *reinterpret_cast<int4*>(&g_deg[e0 + 4]) = make_int4(0, 0, 0, 0);
    }
    int p0 = da.x;
    int p1 = p0 + da.y;
    int p2 = p1 + da.z;
    int p3 = p2 + da.w;
    int p4 = p3 + db.x;
    int p5 = p4 + db.y;
    int p6 = p5 + db.z;
    int p7 = p6 + db.w;                      // thread total

    // block inclusive scan of thread totals
    int incl = p7;
    #pragma unroll
    for (int dd = 1; dd < 32; dd <<= 1) {
        int u = __shfl_up_sync(0xffffffffu, incl, dd);
        if (lane >= dd) incl += u;
    }
    if (lane == 31) ws[wid] = incl;
    __syncthreads();
    if (wid == 0) {
        int s = (lane < 8) ? ws[lane] : 0;
        #pragma unroll
        for (int dd = 1; dd < 8; dd <<= 1) {
            int u = __shfl_up_sync(0xffffffffu, s, dd);
            if (lane >= dd) s += u;
        }
        if (lane < 8) ws[lane] = s;
    }
    __syncthreads();
    int thr_excl = incl - p7 + (wid > 0 ? ws[wid - 1] : 0);
    int total = ws[7];

    // publish aggregate, then warp-parallel lookback (warp 0)
    if (tid == 0) {
        if (b == 0) {
            g_blk_pref[0] = total;
            __threadfence();
            atomicExch(&g_blk_state[0], 2);
        } else {
            g_blk_agg[b] = total;
            __threadfence();
            atomicExch(&g_blk_state[b], 1);
        }
    }
    if (wid == 0) {
        int excl = 0;
        if (b > 0) {
            int hi_end = b;                  // predecessors [0, b), <= 24
            while (hi_end > 0) {
                int start = hi_end - 32 > 0 ? hi_end - 32 : 0;
                int idx = start + lane;
                bool valid = (idx < hi_end);
                int st = 2;
                do {
                    if (valid) st = atomicAdd(&g_blk_state[idx], 0);
                } while (__any_sync(0xffffffffu, valid && st == 0));
                int val = 0;
                if (valid)
                    val = (st == 2) ? atomicAdd(&g_blk_pref[idx], 0)
                                    : atomicAdd(&g_blk_agg[idx], 0);
                unsigned m2 = __ballot_sync(0xffffffffu, valid && st == 2);
                int contrib;
                bool done;
                if (m2) {
                    int hi = 31 - __clz(m2);              // rightmost prefix-ready
                    contrib = (valid && lane >= hi) ? val : 0;
                    done = true;
                } else {
                    contrib = valid ? val : 0;
                    done = false;
                }
                #pragma unroll
                for (int dd = 16; dd > 0; dd >>= 1)
                    contrib += __shfl_down_sync(0xffffffffu, contrib, dd);
                excl += __shfl_sync(0xffffffffu, contrib, 0);
                if (done) break;
                hi_end = start;
            }
            if (lane == 0) {
                g_blk_pref[b] = excl + total;
                __threadfence();
                atomicExch(&g_blk_state[b], 2);
            }
        }
        if (lane == 0) s_excl = excl;
    }
    __syncthreads();

    if (inb0) {
        int base = s_excl + thr_excl;
        int4 oa = make_int4(base, base + p0, base + p1, base + p2);
        int4 ob = make_int4(base + p3, base + p4, base + p5, base + p6);
        *reinterpret_cast<int4*>(&g_off[e0]) = oa;
        *reinterpret_cast<int4*>(&g_off[e0 + 4]) = ob;
    }
    if (b == 0 && tid == 0) g_off[NNODES] = NEDGES;
}

// ---------------------------------------------------------------------------
// K3: fill — NO atomics. pos = off[dst] + rank[e]. 4 edges/thread.
// Also resets the lookback state arrays (after scan has fully completed).
// ---------------------------------------------------------------------------
__global__ __launch_bounds__(256) void fill_kernel(const int* __restrict__ ei) {
    int t = blockIdx.x * blockDim.x + threadIdx.x;
    if (t < NB3) g_blk_state[t] = 0;
    int base = t * 4;
    if (base >= NEDGES) return;
    int4 s = *reinterpret_cast<const int4*>(ei + base);
    int4 d = *reinterpret_cast<const int4*>(ei + NEDGES + base);
    int4 r = *reinterpret_cast<const int4*>(&g_rank[base]);
    int o0 = __ldg(&g_off[d.x]);
    int o1 = __ldg(&g_off[d.y]);
    int o2 = __ldg(&g_off[d.z]);
    int o3 = __ldg(&g_off[d.w]);
    g_srcs[o0 + r.x] = s.x;
    g_srcs[o1 + r.y] = s.y;
    g_srcs[o2 + r.z] = s.z;
    g_srcs[o3 + r.w] = s.w;
}

// ---------------------------------------------------------------------------
// K4: tf32 tensor-core GEMM, double-buffered smem.
// y[m,n] = sum_k x[m,k] * W[n,k] + b[n], fp16 out.
// ---------------------------------------------------------------------------
#define GBM 128
#define GBK 16
#define SSTRIDE 136
#define NTILES (IN_C / GBK)   // 16

__device__ __forceinline__ uint32_t f32_to_tf32(float f) {
    uint32_t r;
    asm("cvt.rna.tf32.f32 %0, %1;" : "=r"(r) : "f"(f));
    return r;
}

__global__ __launch_bounds__(256, 2) void gemm_tf32_kernel(
    const float* __restrict__ x,
    const float* __restrict__ W,
    const float* __restrict__ b)
{
    __shared__ uint32_t As[2][GBK * SSTRIDE];
    __shared__ uint32_t Bs[2][GBK * SSTRIDE];

    const int tid  = threadIdx.x;
    const int lane = tid & 31;
    const int warp = tid >> 5;
    const int wm   = warp >> 1;
    const int wn   = warp & 1;
    const int block_m = blockIdx.x * GBM;
    const int grp = lane >> 2;
    const int qid = lane & 3;

    const int idx0 = tid * 2;
    const int row0 = idx0 >> 2;
    const int kq0  = (idx0 & 3) * 4;
    const int row1 = (idx0 + 1) >> 2;
    const int kq1  = ((idx0 + 1) & 3) * 4;
    const int gm0 = block_m + row0;
    const int gm1 = block_m + row1;
    const bool ok0 = (gm0 < NNODES);
    const bool ok1 = (gm1 < NNODES);

    float acc[2][8][4];
    #pragma unroll
    for (int i = 0; i < 2; i++)
        #pragma unroll
        for (int j = 0; j < 8; j++)
            #pragma unroll
            for (int c = 0; c < 4; c++)
                acc[i][j][c] = 0.f;

    float4 pa0, pa1, pb0, pb1;

    pa0 = ok0 ? *reinterpret_cast<const float4*>(x + (size_t)gm0 * IN_C + kq0)
              : make_float4(0.f, 0.f, 0.f, 0.f);
    pa1 = ok1 ? *reinterpret_cast<const float4*>(x + (size_t)gm1 * IN_C + kq1)
              : make_float4(0.f, 0.f, 0.f, 0.f);
    pb0 = *reinterpret_cast<const float4*>(W + (size_t)row0 * IN_C + kq0);
    pb1 = *reinterpret_cast<const float4*>(W + (size_t)row1 * IN_C + kq1);

    {
        As[0][(kq0 + 0) * SSTRIDE + row0] = f32_to_tf32(pa0.x);
        As[0][(kq0 + 1) * SSTRIDE + row0] = f32_to_tf32(pa0.y);
        As[0][(kq0 + 2) * SSTRIDE + row0] = f32_to_tf32(pa0.z);
        As[0][(kq0 + 3) * SSTRIDE + row0] = f32_to_tf32(pa0.w);
        As[0][(kq1 + 0) * SSTRIDE + row1] = f32_to_tf32(pa1.x);
        As[0][(kq1 + 1) * SSTRIDE + row1] = f32_to_tf32(pa1.y);
        As[0][(kq1 + 2) * SSTRIDE + row1] = f32_to_tf32(pa1.z);
        As[0][(kq1 + 3) * SSTRIDE + row1] = f32_to_tf32(pa1.w);
        Bs[0][(kq0 + 0) * SSTRIDE + row0] = f32_to_tf32(pb0.x);
        Bs[0][(kq0 + 1) * SSTRIDE + row0] = f32_to_tf32(pb0.y);
        Bs[0][(kq0 + 2) * SSTRIDE + row0] = f32_to_tf32(pb0.z);
        Bs[0][(kq0 + 3) * SSTRIDE + row0] = f32_to_tf32(pb0.w);
        Bs[0][(kq1 + 0) * SSTRIDE + row1] = f32_to_tf32(pb1.x);
        Bs[0][(kq1 + 1) * SSTRIDE + row1] = f32_to_tf32(pb1.y);
        Bs[0][(kq1 + 2) * SSTRIDE + row1] = f32_to_tf32(pb1.z);
        Bs[0][(kq1 + 3) * SSTRIDE + row1] = f32_to_tf32(pb1.w);
    }
    __syncthreads();

    for (int t = 0; t < NTILES; t++) {
        const int cur = t & 1;
        const bool has_next = (t + 1 < NTILES);

        if (has_next) {
            int k0 = (t + 1) * GBK;
            pa0 = ok0 ? *reinterpret_cast<const float4*>(x + (size_t)gm0 * IN_C + k0 + kq0)
                      : make_float4(0.f, 0.f, 0.f, 0.f);
            pa1 = ok1 ? *reinterpret_cast<const float4*>(x + (size_t)gm1 * IN_C + k0 + kq1)
                      : make_float4(0.f, 0.f, 0.f, 0.f);
            pb0 = *reinterpret_cast<const float4*>(W + (size_t)row0 * IN_C + k0 + kq0);
            pb1 = *reinterpret_cast<const float4*>(W + (size_t)row1 * IN_C + k0 + kq1);
        }

        #pragma unroll
        for (int s = 0; s < 2; s++) {
            const int kk = s * 8 + qid;

            uint32_t af[2][4];
            #pragma unroll
            for (int i = 0; i < 2; i++) {
                int rm = wm * 32 + i * 16 + grp;
                af[i][0] = As[cur][kk * SSTRIDE + rm];
                af[i][1] = As[cur][kk * SSTRIDE + rm + 8];
                af[i][2] = As[cur][(kk + 4) * SSTRIDE + rm];
                af[i][3] = As[cur][(kk + 4) * SSTRIDE + rm + 8];
            }
            uint32_t bf[8][2];
            #pragma unroll
            for (int j = 0; j < 8; j++) {
                int bn = wn * 64 + j * 8 + grp;
                bf[j][0] = Bs[cur][kk * SSTRIDE + bn];
                bf[j][1] = Bs[cur][(kk + 4) * SSTRIDE + bn];
            }
            #pragma unroll
            for (int i = 0; i < 2; i++)
                #pragma unroll
                for (int j = 0; j < 8; j++) {
                    asm volatile(
                        "mma.sync.aligned.m16n8k8.row.col.f32.tf32.tf32.f32 "
                        "{%0,%1,%2,%3}, {%4,%5,%6,%7}, {%8,%9}, {%0,%1,%2,%3};\n"
                        : "+f"(acc[i][j][0]), "+f"(acc[i][j][1]),
                          "+f"(acc[i][j][2]), "+f"(acc[i][j][3])
                        : "r"(af[i][0]), "r"(af[i][1]), "r"(af[i][2]), "r"(af[i][3]),
                          "r"(bf[j][0]), "r"(bf[j][1]));
                }
        }

        if (has_next) {
            const int nxt = cur ^ 1;
            As[nxt][(kq0 + 0) * SSTRIDE + row0] = f32_to_tf32(pa0.x);
            As[nxt][(kq0 + 1) * SSTRIDE + row0] = f32_to_tf32(pa0.y);
            As[nxt][(kq0 + 2) * SSTRIDE + row0] = f32_to_tf32(pa0.z);
            As[nxt][(kq0 + 3) * SSTRIDE + row0] = f32_to_tf32(pa0.w);
            As[nxt][(kq1 + 0) * SSTRIDE + row1] = f32_to_tf32(pa1.x);
            As[nxt][(kq1 + 1) * SSTRIDE + row1] = f32_to_tf32(pa1.y);
            As[nxt][(kq1 + 2) * SSTRIDE + row1] = f32_to_tf32(pa1.z);
            As[nxt][(kq1 + 3) * SSTRIDE + row1] = f32_to_tf32(pa1.w);
            Bs[nxt][(kq0 + 0) * SSTRIDE + row0] = f32_to_tf32(pb0.x);
            Bs[nxt][(kq0 + 1) * SSTRIDE + row0] = f32_to_tf32(pb0.y);
            Bs[nxt][(kq0 + 2) * SSTRIDE + row0] = f32_to_tf32(pb0.z);
            Bs[nxt][(kq0 + 3) * SSTRIDE + row0] = f32_to_tf32(pb0.w);
            Bs[nxt][(kq1 + 0) * SSTRIDE + row1] = f32_to_tf32(pb1.x);
            Bs[nxt][(kq1 + 1) * SSTRIDE + row1] = f32_to_tf32(pb1.y);
            Bs[nxt][(kq1 + 2) * SSTRIDE + row1] = f32_to_tf32(pb1.z);
            Bs[nxt][(kq1 + 3) * SSTRIDE + row1] = f32_to_tf32(pb1.w);
            __syncthreads();
        }
    }

    #pragma unroll
    for (int i = 0; i < 2; i++) {
        int r0 = block_m + wm * 32 + i * 16 + grp;
        int r1 = r0 + 8;
        #pragma unroll
        for (int j = 0; j < 8; j++) {
            int col = wn * 64 + j * 8 + qid * 2;
            float b0 = b[col], b1 = b[col + 1];
            if (r0 < NNODES) {
                __half2 h = __floats2half2_rn(acc[i][j][0] + b0, acc[i][j][1] + b1);
                *reinterpret_cast<__half2*>(&g_y[(size_t)r0 * OUT_C + col]) = h;
            }
            if (r1 < NNODES) {
                __half2 h = __floats2half2_rn(acc[i][j][2] + b0, acc[i][j][3] + b1);
                *reinterpret_cast<__half2*>(&g_y[(size_t)r1 * OUT_C + col]) = h;
            }
        }
    }
}

// ---------------------------------------------------------------------------
// K5: gather + mean. 2 nodes per warp; 16 lanes per node; one uint4 (8 halfs)
// per lane. fp32 accumulation, unrolled x8 for MLP.
// ---------------------------------------------------------------------------
__device__ __forceinline__ void acc_row(float* acc, uint4 v) {
    float2 f;
    f = __half22float2(*reinterpret_cast<__half2*>(&v.x)); acc[0] += f.x; acc[1] += f.y;
    f = __half22float2(*reinterpret_cast<__half2*>(&v.y)); acc[2] += f.x; acc[3] += f.y;
    f = __half22float2(*reinterpret_cast<__half2*>(&v.z)); acc[4] += f.x; acc[5] += f.y;
    f = __half22float2(*reinterpret_cast<__half2*>(&v.w)); acc[6] += f.x; acc[7] += f.y;
}

__global__ __launch_bounds__(256) void gather_kernel(float* __restrict__ out) {
    int warp_id = (blockIdx.x * blockDim.x + threadIdx.x) >> 5;
    int lane = threadIdx.x & 31;
    int half_id = lane >> 4;
    int sub = lane & 15;
    int node = warp_id * 2 + half_id;
    if (node >= NNODES) return;

    int s = g_off[node];
    int e = g_off[node + 1];

    float acc[8];
    #pragma unroll
    for (int c = 0; c < 8; c++) acc[c] = 0.f;

    const size_t loff = (size_t)sub * 8;

    int i = s;
    for (; i + 7 < e; i += 8) {
        int sn[8];
        #pragma unroll
        for (int q = 0; q < 8; q++) sn[q] = __ldg(&g_srcs[i + q]);
        uint4 v[8];
        #pragma unroll
        for (int q = 0; q < 8; q++)
            v[q] = *reinterpret_cast<const uint4*>(&g_y[(size_t)sn[q] * OUT_C + loff]);
        #pragma unroll
        for (int q = 0; q < 8; q++) acc_row(acc, v[q]);
    }
    for (; i + 3 < e; i += 4) {
        int sn[4];
        #pragma unroll
        for (int q = 0; q < 4; q++) sn[q] = __ldg(&g_srcs[i + q]);
        uint4 v[4];
        #pragma unroll
        for (int q = 0; q < 4; q++)
            v[q] = *reinterpret_cast<const uint4*>(&g_y[(size_t)sn[q] * OUT_C + loff]);
        #pragma unroll
        for (int q = 0; q < 4; q++) acc_row(acc, v[q]);
    }
    for (; i < e; i++) {
        int s0 = __ldg(&g_srcs[i]);
        uint4 v = *reinterpret_cast<const uint4*>(&g_y[(size_t)s0 * OUT_C + loff]);
        acc_row(acc, v);
    }

    float inv = 1.0f / (float)max(e - s, 1);
    float4 o0 = make_float4(acc[0] * inv, acc[1] * inv, acc[2] * inv, acc[3] * inv);
    float4 o1 = make_float4(acc[4] * inv, acc[5] * inv, acc[6] * inv, acc[7] * inv);
    float* op = out + (size_t)node * OUT_C + loff;
    *reinterpret_cast<float4*>(op) = o0;
    *reinterpret_cast<float4*>(op + 4) = o1;
}

// ---------------------------------------------------------------------------
extern "C" void kernel_launch(void* const* d_in, const int* in_sizes, int n_in,
                              void* d_out, int out_size) {
    const float* x  = (const float*)d_in[0];
    const int*   ei = (const int*)d_in[1];
    const float* W  = (const float*)d_in[2];
    const float* b  = (const float*)d_in[3];
    float* out = (float*)d_out;

    static cudaStream_t s_gemm = nullptr;
    static cudaEvent_t ev_fork = nullptr, ev_join = nullptr;
    if (!s_gemm) {
        cudaStreamCreateWithFlags(&s_gemm, cudaStreamNonBlocking);
        cudaEventCreateWithFlags(&ev_fork, cudaEventDisableTiming);
        cudaEventCreateWithFlags(&ev_join, cudaEventDisableTiming);
    }

    int edge_blocks4 = (NEDGES / 4 + 255) / 256;   // 4 edges per thread

    // Fork: GEMM on side stream (independent of CSR build)
    cudaEventRecord(ev_fork, 0);
    cudaStreamWaitEvent(s_gemm, ev_fork, 0);
    gemm_tf32_kernel<<<(NNODES + GBM - 1) / GBM, 256, 0, s_gemm>>>(x, W, b);
    cudaEventRecord(ev_join, s_gemm);

    // CSR build on main stream (g_deg, g_blk_state are zero at entry)
    rank_kernel<<<edge_blocks4, 256>>>(ei);
    scan_lookback_kernel<<<NB3, 256>>>();
    fill_kernel<<<edge_blocks4, 256>>>(ei);

    // Join, then gather + mean
    cudaStreamWaitEvent(0, ev_join, 0);
    gather_kernel<<<(NNODES / 2 * 32 + 255) / 256, 256>>>(out);
}